// round 3
// baseline (speedup 1.0000x reference)
#include <cuda_runtime.h>
#include <cuda_bf16.h>
#include <cstdint>

#define N_NODES 20000
#define N_EDGES 320000
#define ET      (N_EDGES + N_NODES)   // with self loops = 340000
#define GCN_IN  256
#define C1      128
#define H1      5
#define F1      (H1*C1)               // 640
#define C2      128
#define H2      3
#define F2      (H2*C2)               // 384
#define N_BBOX  4096

// ---------------- scratch (device globals; no allocation allowed) ----------
__device__ int   g_is64;              // 1 if index inputs are int64, 0 if int32
__device__ int   g_cnt[N_NODES];
__device__ int   g_cur[N_NODES];
__device__ int   g_off[N_NODES + 1];
__device__ int   g_src[ET];
__device__ float g_h1[(size_t)N_NODES * F1];     // x @ W1
__device__ float g_o1[(size_t)N_NODES * F1];     // layer1 output (post leaky)
__device__ float g_h2[(size_t)N_NODES * F2];     // o1 @ W2
__device__ float g_as1[N_NODES * H1];
__device__ float g_ad1[N_NODES * H1];
__device__ float g_as2[N_NODES * H2];
__device__ float g_ad2[N_NODES * H2];
__device__ float g_alpha1[(size_t)ET * H1];
__device__ float g_alpha2[(size_t)ET * H2];

__device__ __forceinline__ float leaky(float x, float s) {
    return x >= 0.f ? x : s * x;
}

__device__ __forceinline__ int load_idx(const void* p, long long i) {
    return g_is64 ? (int)((const long long*)p)[i] : ((const int*)p)[i];
}

// ---------------- dtype sniff ----------------------------------------------
// int64 little-endian: odd 32-bit words are high halves == 0 (values < 20000).
// int32: odd words are uniform node ids; all-64-zero probability ~ 0.
__global__ void k_detect(const void* ei) {
    const int* p = (const int*)ei;
    int nz = 0;
    #pragma unroll
    for (int i = 0; i < 64; i++) nz |= p[2 * i + 1];
    g_is64 = (nz == 0) ? 1 : 0;
}

// ---------------- CSR build ------------------------------------------------
__global__ void k_zero() {
    int i = blockIdx.x * blockDim.x + threadIdx.x;
    if (i < N_NODES) { g_cnt[i] = 0; g_cur[i] = 0; }
}

__global__ void k_hist(const void* __restrict__ ei) {
    int e = blockIdx.x * blockDim.x + threadIdx.x;
    if (e >= ET) return;
    int dst = (e < N_EDGES) ? load_idx(ei, (long long)N_EDGES + e) : (e - N_EDGES);
    atomicAdd(&g_cnt[dst], 1);
}

__global__ void k_scan() {
    __shared__ int warpsum[32];
    __shared__ int carry_sh;
    int tid = threadIdx.x;
    int lane = tid & 31, wid = tid >> 5;
    if (tid == 0) { g_off[0] = 0; carry_sh = 0; }
    __syncthreads();
    const int CH = (N_NODES + 1023) / 1024;
    for (int c = 0; c < CH; c++) {
        int i = c * 1024 + tid;
        int v = (i < N_NODES) ? g_cnt[i] : 0;
        int x = v;
        #pragma unroll
        for (int o = 1; o < 32; o <<= 1) {
            int y = __shfl_up_sync(~0u, x, o);
            if (lane >= o) x += y;
        }
        if (lane == 31) warpsum[wid] = x;
        __syncthreads();
        if (wid == 0) {
            int w = warpsum[lane];
            #pragma unroll
            for (int o = 1; o < 32; o <<= 1) {
                int y = __shfl_up_sync(~0u, w, o);
                if (lane >= o) w += y;
            }
            warpsum[lane] = w;
        }
        __syncthreads();
        int incl = x + (wid > 0 ? warpsum[wid - 1] : 0);
        int total = warpsum[31];
        if (i < N_NODES) g_off[i + 1] = carry_sh + incl;
        __syncthreads();
        if (tid == 0) carry_sh += total;
        __syncthreads();
    }
}

__global__ void k_scatter(const void* __restrict__ ei) {
    int e = blockIdx.x * blockDim.x + threadIdx.x;
    if (e >= ET) return;
    int src, dst;
    if (e < N_EDGES) {
        src = load_idx(ei, e);
        dst = load_idx(ei, (long long)N_EDGES + e);
    } else {
        src = dst = e - N_EDGES;
    }
    int p = g_off[dst] + atomicAdd(&g_cur[dst], 1);
    g_src[p] = src;
}

// ---------------- SGEMM: C[M,N] = A[M,K] @ B[K,N] --------------------------
// MODE 0: A = x (param),  B = W1 (param), C = g_h1, N=640, K=256
// MODE 1: A = g_o1,       B = W2 (param), C = g_h2, N=384, K=640
template<int MODE>
__global__ void sgemm(const float* __restrict__ Ain, const float* __restrict__ B) {
    const int BM = 128, BN = 64, BK = 16;
    const int M = N_NODES;
    const int N = (MODE == 0) ? F1 : F2;
    const int K = (MODE == 0) ? GCN_IN : F1;
    const float* A = (MODE == 0) ? Ain : (const float*)g_o1;
    float* C = (MODE == 0) ? g_h1 : g_h2;

    __shared__ float As[BK][BM];
    __shared__ float Bs[BK][BN];
    int tid = threadIdx.x;
    int tx = tid & 15;        // col group (TN=4)
    int ty = tid >> 4;        // row group (TM=8)
    int rb = blockIdx.y * BM, cb = blockIdx.x * BN;

    int aRow = tid >> 1;            // 0..127
    int aK   = (tid & 1) * 8;       // 0 or 8
    int bRow = tid >> 4;            // 0..15
    int bCol = (tid & 15) * 4;

    float acc[8][4];
    #pragma unroll
    for (int i = 0; i < 8; i++)
        #pragma unroll
        for (int j = 0; j < 4; j++) acc[i][j] = 0.f;

    for (int k0 = 0; k0 < K; k0 += BK) {
        float4 av0 = make_float4(0, 0, 0, 0), av1 = make_float4(0, 0, 0, 0);
        if (rb + aRow < M) {
            const float* ap = A + (size_t)(rb + aRow) * K + k0 + aK;
            av0 = *reinterpret_cast<const float4*>(ap);
            av1 = *reinterpret_cast<const float4*>(ap + 4);
        }
        As[aK + 0][aRow] = av0.x; As[aK + 1][aRow] = av0.y;
        As[aK + 2][aRow] = av0.z; As[aK + 3][aRow] = av0.w;
        As[aK + 4][aRow] = av1.x; As[aK + 5][aRow] = av1.y;
        As[aK + 6][aRow] = av1.z; As[aK + 7][aRow] = av1.w;
        float4 bv = *reinterpret_cast<const float4*>(B + (size_t)(k0 + bRow) * N + cb + bCol);
        *reinterpret_cast<float4*>(&Bs[bRow][bCol]) = bv;
        __syncthreads();
        #pragma unroll
        for (int k = 0; k < BK; k++) {
            float ra[8], rbv[4];
            #pragma unroll
            for (int i = 0; i < 8; i++) ra[i] = As[k][ty * 8 + i];
            #pragma unroll
            for (int j = 0; j < 4; j++) rbv[j] = Bs[k][tx * 4 + j];
            #pragma unroll
            for (int i = 0; i < 8; i++)
                #pragma unroll
                for (int j = 0; j < 4; j++) acc[i][j] += ra[i] * rbv[j];
        }
        __syncthreads();
    }
    #pragma unroll
    for (int i = 0; i < 8; i++) {
        int r = rb + ty * 8 + i;
        if (r < M)
            *reinterpret_cast<float4*>(C + (size_t)r * N + cb + tx * 4) =
                make_float4(acc[i][0], acc[i][1], acc[i][2], acc[i][3]);
    }
}

// ---------------- attention logits a_s, a_d --------------------------------
template<int MODE>
__global__ void k_att(const float* __restrict__ asrc, const float* __restrict__ adst) {
    const int H = (MODE == 0) ? H1 : H2;
    const float* h = (MODE == 0) ? (const float*)g_h1 : (const float*)g_h2;
    float* oas = (MODE == 0) ? g_as1 : g_as2;
    float* oad = (MODE == 0) ? g_ad1 : g_ad2;
    int w = (blockIdx.x * blockDim.x + threadIdx.x) >> 5;
    int lane = threadIdx.x & 31;
    if (w >= N_NODES * H) return;
    int n = w / H, hh = w % H;
    const float* hp = h + (size_t)n * (H * 128) + hh * 128;
    const float* ap = asrc + hh * 128;
    const float* bp = adst + hh * 128;
    float s = 0.f, d = 0.f;
    #pragma unroll
    for (int j = 0; j < 4; j++) {
        float v = hp[lane + 32 * j];
        s += v * ap[lane + 32 * j];
        d += v * bp[lane + 32 * j];
    }
    #pragma unroll
    for (int o = 16; o; o >>= 1) {
        s += __shfl_xor_sync(~0u, s, o);
        d += __shfl_xor_sync(~0u, d, o);
    }
    if (lane == 0) { oas[w] = s; oad[w] = d; }
}

// ---------------- segment softmax (warp per node, 3 passes) ----------------
template<int MODE>
__global__ void k_softmax() {
    const int H = (MODE == 0) ? H1 : H2;
    const float* as_ = (MODE == 0) ? (const float*)g_as1 : (const float*)g_as2;
    const float* ad_ = (MODE == 0) ? (const float*)g_ad1 : (const float*)g_ad2;
    float* alpha = (MODE == 0) ? g_alpha1 : g_alpha2;
    int n = (blockIdx.x * blockDim.x + threadIdx.x) >> 5;
    int lane = threadIdx.x & 31;
    if (n >= N_NODES) return;
    int beg = g_off[n], end = g_off[n + 1];
    float ad[H1], m[H1], dsum[H1];   // H1 >= H2
    #pragma unroll
    for (int h = 0; h < H; h++) { ad[h] = ad_[n * H + h]; m[h] = -1e30f; dsum[h] = 0.f; }
    for (int i = beg + lane; i < end; i += 32) {
        int s = g_src[i];
        #pragma unroll
        for (int h = 0; h < H; h++) {
            float e = as_[s * H + h] + ad[h];
            e = leaky(e, 0.2f);
            alpha[(size_t)i * H + h] = e;
            m[h] = fmaxf(m[h], e);
        }
    }
    #pragma unroll
    for (int h = 0; h < H; h++)
        #pragma unroll
        for (int o = 16; o; o >>= 1) m[h] = fmaxf(m[h], __shfl_xor_sync(~0u, m[h], o));
    for (int i = beg + lane; i < end; i += 32) {
        #pragma unroll
        for (int h = 0; h < H; h++) {
            float ex = expf(alpha[(size_t)i * H + h] - m[h]);
            alpha[(size_t)i * H + h] = ex;
            dsum[h] += ex;
        }
    }
    #pragma unroll
    for (int h = 0; h < H; h++)
        #pragma unroll
        for (int o = 16; o; o >>= 1) dsum[h] += __shfl_xor_sync(~0u, dsum[h], o);
    float rinv[H1];
    #pragma unroll
    for (int h = 0; h < H; h++) rinv[h] = 1.f / (dsum[h] + 1e-16f);
    for (int i = beg + lane; i < end; i += 32) {
        #pragma unroll
        for (int h = 0; h < H; h++)
            alpha[(size_t)i * H + h] *= rinv[h];
    }
}

// ---------------- layer-1 aggregation (block per node) ---------------------
__global__ void k_agg1(const float* __restrict__ b1) {
    int n = blockIdx.x;
    int t = threadIdx.x;   // 0..127
    int beg = g_off[n], end = g_off[n + 1];
    float acc[H1] = {0.f, 0.f, 0.f, 0.f, 0.f};
    for (int i = beg; i < end; i++) {
        int s = g_src[i];
        float a[H1];
        #pragma unroll
        for (int h = 0; h < H1; h++) a[h] = g_alpha1[(size_t)i * H1 + h];
        const float* hp = g_h1 + (size_t)s * F1;
        #pragma unroll
        for (int h = 0; h < H1; h++) acc[h] += a[h] * hp[h * 128 + t];
    }
    #pragma unroll
    for (int h = 0; h < H1; h++) {
        float v = acc[h] + b1[h * 128 + t];
        g_o1[(size_t)n * F1 + h * 128 + t] = leaky(v, 0.01f);
    }
}

// ---------------- layer-2 aggregation: ONLY at bbox entries ----------------
__global__ void k_agg2(const void* __restrict__ bbox, const float* __restrict__ b2,
                       float* __restrict__ out) {
    int i = blockIdx.x;
    int t = threadIdx.x;   // 0..127
    int n = load_idx(bbox, i);
    int beg = g_off[n], end = g_off[n + 1];
    float a0 = 0.f, a1 = 0.f, a2 = 0.f;
    for (int e = beg; e < end; e++) {
        int s = g_src[e];
        float al0 = g_alpha2[(size_t)e * H2 + 0];
        float al1 = g_alpha2[(size_t)e * H2 + 1];
        float al2 = g_alpha2[(size_t)e * H2 + 2];
        const float* hp = g_h2 + (size_t)s * F2;
        a0 += al0 * hp[t];
        a1 += al1 * hp[128 + t];
        a2 += al2 * hp[256 + t];
    }
    float v = (a0 + a1 + a2) * (1.f / 3.f) + b2[t];
    out[(size_t)i * 128 + t] = leaky(v, 0.01f);
}

// ---------------- launch ---------------------------------------------------
extern "C" void kernel_launch(void* const* d_in, const int* in_sizes, int n_in,
                              void* d_out, int out_size) {
    // Map inputs by element count (robust to ordering). Equal-size groups
    // keep relative order: 640: att_src1, att_dst1, b1 | 384: att_src2, att_dst2
    const float *x = nullptr, *W1 = nullptr, *W2 = nullptr, *b1 = nullptr, *b2 = nullptr;
    const float *att_src1 = nullptr, *att_dst1 = nullptr;
    const float *att_src2 = nullptr, *att_dst2 = nullptr;
    const void *ei = nullptr, *bbox = nullptr;
    int n640 = 0, n384 = 0;
    for (int i = 0; i < n_in; i++) {
        switch (in_sizes[i]) {
            case N_NODES * GCN_IN: x    = (const float*)d_in[i]; break;
            case 2 * N_EDGES:      ei   = d_in[i]; break;
            case N_BBOX:           bbox = d_in[i]; break;
            case GCN_IN * F1:      W1   = (const float*)d_in[i]; break;
            case F1 * F2:          W2   = (const float*)d_in[i]; break;
            case C2:               b2   = (const float*)d_in[i]; break;
            case F1:
                if      (n640 == 0) att_src1 = (const float*)d_in[i];
                else if (n640 == 1) att_dst1 = (const float*)d_in[i];
                else                b1       = (const float*)d_in[i];
                n640++; break;
            case F2:
                if (n384 == 0) att_src2 = (const float*)d_in[i];
                else           att_dst2 = (const float*)d_in[i];
                n384++; break;
            default: break;
        }
    }
    float* out = (float*)d_out;

    // dtype sniff + CSR build
    k_detect<<<1, 1>>>(ei);
    k_zero<<<(N_NODES + 255) / 256, 256>>>();
    k_hist<<<(ET + 255) / 256, 256>>>(ei);
    k_scan<<<1, 1024>>>();
    k_scatter<<<(ET + 255) / 256, 256>>>(ei);

    // layer 1
    {
        dim3 g(F1 / 64, (N_NODES + 127) / 128);
        sgemm<0><<<g, 256>>>(x, W1);
    }
    k_att<0><<<(N_NODES * H1 * 32 + 255) / 256, 256>>>(att_src1, att_dst1);
    k_softmax<0><<<(N_NODES * 32 + 255) / 256, 256>>>();
    k_agg1<<<N_NODES, 128>>>(b1);

    // layer 2
    {
        dim3 g(F2 / 64, (N_NODES + 127) / 128);
        sgemm<1><<<g, 256>>>(nullptr, W2);
    }
    k_att<1><<<(N_NODES * H2 * 32 + 255) / 256, 256>>>(att_src2, att_dst2);
    k_softmax<1><<<(N_NODES * 32 + 255) / 256, 256>>>();
    k_agg2<<<N_BBOX, 128>>>(bbox, b2, out);
}

// round 4
// speedup vs baseline: 1.4161x; 1.4161x over previous
#include <cuda_runtime.h>
#include <cuda_bf16.h>
#include <cstdint>

#define N_NODES 20000
#define N_EDGES 320000
#define ET      (N_EDGES + N_NODES)   // 340000
#define GCN_IN  256
#define C1      128
#define H1      5
#define F1      (H1*C1)               // 640
#define C2      128
#define H2      3
#define F2      (H2*C2)               // 384
#define N_BBOX  4096
#define NB_SCAN ((N_NODES + 1023) / 1024)   // 20

// ---------------- scratch ---------------------------------------------------
__device__ int   g_is64;
__device__ int   g_cnt[N_NODES];
__device__ int   g_cur[N_NODES];
__device__ int   g_off[N_NODES + 1];
__device__ int   g_src[ET];
__device__ int   g_bsum[32];
__device__ int   g_bpre[32];
__device__ float g_h1[(size_t)N_NODES * F1];
__device__ float g_o1[(size_t)N_NODES * F1];
__device__ float g_h2[(size_t)N_NODES * F2];
__device__ float g_as1[N_NODES * H1];
__device__ float g_ad1[N_NODES * H1];
__device__ float g_as2[N_NODES * H2];
__device__ float g_ad2[N_NODES * H2];
__device__ float g_alpha1[(size_t)ET * H1];
__device__ float g_alpha2[(size_t)ET * H2];

__device__ __forceinline__ float leaky(float x, float s) {
    return x >= 0.f ? x : s * x;
}
__device__ __forceinline__ int load_idx(const void* p, long long i) {
    return g_is64 ? (int)((const long long*)p)[i] : ((const int*)p)[i];
}
__device__ __forceinline__ uint32_t f2tf32(float x) {
    uint32_t u;
    asm("cvt.rna.tf32.f32 %0, %1;" : "=r"(u) : "f"(x));
    return u;
}

// ---------------- dtype sniff -----------------------------------------------
__global__ void k_detect(const void* ei) {
    const int* p = (const int*)ei;
    int nz = 0;
    #pragma unroll
    for (int i = 0; i < 64; i++) nz |= p[2 * i + 1];
    g_is64 = (nz == 0) ? 1 : 0;
}

// ---------------- CSR build -------------------------------------------------
__global__ void k_zero() {
    int i = blockIdx.x * blockDim.x + threadIdx.x;
    if (i < N_NODES) { g_cnt[i] = 0; g_cur[i] = 0; }
}

__global__ void k_hist(const void* __restrict__ ei) {
    int e = blockIdx.x * blockDim.x + threadIdx.x;
    if (e >= ET) return;
    int dst = (e < N_EDGES) ? load_idx(ei, (long long)N_EDGES + e) : (e - N_EDGES);
    atomicAdd(&g_cnt[dst], 1);
}

// 3-phase grid scan: per-block inclusive, block sums, add prefix
__global__ void k_scan1() {
    __shared__ int ws[32];
    int tid = threadIdx.x, lane = tid & 31, wid = tid >> 5;
    int i = blockIdx.x * 1024 + tid;
    int v = (i < N_NODES) ? g_cnt[i] : 0;
    int x = v;
    #pragma unroll
    for (int o = 1; o < 32; o <<= 1) {
        int y = __shfl_up_sync(~0u, x, o);
        if (lane >= o) x += y;
    }
    if (lane == 31) ws[wid] = x;
    __syncthreads();
    if (wid == 0) {
        int w = ws[lane];
        #pragma unroll
        for (int o = 1; o < 32; o <<= 1) {
            int y = __shfl_up_sync(~0u, w, o);
            if (lane >= o) w += y;
        }
        ws[lane] = w;
    }
    __syncthreads();
    int incl = x + (wid > 0 ? ws[wid - 1] : 0);
    if (i < N_NODES) g_off[i + 1] = incl;
    if (tid == 1023) g_bsum[blockIdx.x] = incl;
}

__global__ void k_scan2() {
    int lane = threadIdx.x;
    int v = (lane < NB_SCAN) ? g_bsum[lane] : 0;
    int x = v;
    #pragma unroll
    for (int o = 1; o < 32; o <<= 1) {
        int y = __shfl_up_sync(~0u, x, o);
        if (lane >= o) x += y;
    }
    g_bpre[lane] = x - v;   // exclusive prefix
}

__global__ void k_scan3() {
    int i = blockIdx.x * 1024 + threadIdx.x;
    if (i == 0) g_off[0] = 0;
    if (i < N_NODES) g_off[i + 1] += g_bpre[blockIdx.x];
}

__global__ void k_scatter(const void* __restrict__ ei) {
    int e = blockIdx.x * blockDim.x + threadIdx.x;
    if (e >= ET) return;
    int src, dst;
    if (e < N_EDGES) {
        src = load_idx(ei, e);
        dst = load_idx(ei, (long long)N_EDGES + e);
    } else {
        src = dst = e - N_EDGES;
    }
    int p = g_off[dst] + atomicAdd(&g_cur[dst], 1);
    g_src[p] = src;
}

// ---------------- TF32 tensor-core GEMM ------------------------------------
// C[M,N] = A[M,K] @ B[K,N], row-major fp32 in/out, tf32 mma.
// BM=128 BN=64 BK=32; 256 threads = 8 warps (4 in M x 2 in N), warp tile 32x32.
// MODE 0: A=x,    B=W1, C=g_h1, N=640, K=256
// MODE 1: A=g_o1, B=W2, C=g_h2, N=384, K=640
template<int MODE>
__global__ void gemm_tf32(const float* __restrict__ Ain, const float* __restrict__ B) {
    const int M = N_NODES;
    const int N = (MODE == 0) ? F1 : F2;
    const int K = (MODE == 0) ? GCN_IN : F1;
    const float* A = (MODE == 0) ? Ain : (const float*)g_o1;
    float* C = (MODE == 0) ? g_h1 : g_h2;

    const int BM = 128, BN = 64, BK = 32;
    __shared__ uint32_t As[BK][BM + 4];   // [k][m], tf32 bits
    __shared__ uint32_t Bs[BK][BN + 4];   // [k][n], tf32 bits

    int tid = threadIdx.x;
    int lane = tid & 31, warp = tid >> 5;
    int warp_m = (warp & 3) * 32;
    int warp_n = (warp >> 2) * 32;
    int rb = blockIdx.y * BM, cb = blockIdx.x * BN;

    int grp = lane >> 2;     // 0..7
    int sub = lane & 3;      // 0..3

    float acc[2][4][4];
    #pragma unroll
    for (int i = 0; i < 2; i++)
        #pragma unroll
        for (int j = 0; j < 4; j++)
            #pragma unroll
            for (int q = 0; q < 4; q++) acc[i][j][q] = 0.f;

    for (int k0 = 0; k0 < K; k0 += BK) {
        // load A tile (128x32) -> As[k][m], converted to tf32
        #pragma unroll
        for (int p = 0; p < 4; p++) {
            int r = p * 32 + (tid >> 3);
            int c = (tid & 7) * 4;
            float4 v = make_float4(0, 0, 0, 0);
            if (rb + r < M)
                v = *reinterpret_cast<const float4*>(A + (size_t)(rb + r) * K + k0 + c);
            As[c + 0][r] = f2tf32(v.x);
            As[c + 1][r] = f2tf32(v.y);
            As[c + 2][r] = f2tf32(v.z);
            As[c + 3][r] = f2tf32(v.w);
        }
        // load B tile (32x64) -> Bs[k][n]
        #pragma unroll
        for (int p = 0; p < 2; p++) {
            int r = p * 16 + (tid >> 4);
            int c = (tid & 15) * 4;
            float4 v = *reinterpret_cast<const float4*>(B + (size_t)(k0 + r) * N + cb + c);
            Bs[r][c + 0] = f2tf32(v.x);
            Bs[r][c + 1] = f2tf32(v.y);
            Bs[r][c + 2] = f2tf32(v.z);
            Bs[r][c + 3] = f2tf32(v.w);
        }
        __syncthreads();

        #pragma unroll
        for (int kk = 0; kk < 4; kk++) {
            int kb = kk * 8;
            uint32_t a[2][4];
            #pragma unroll
            for (int mt = 0; mt < 2; mt++) {
                int mr = warp_m + mt * 16;
                a[mt][0] = As[kb + sub    ][mr + grp    ];
                a[mt][1] = As[kb + sub    ][mr + grp + 8];
                a[mt][2] = As[kb + sub + 4][mr + grp    ];
                a[mt][3] = As[kb + sub + 4][mr + grp + 8];
            }
            #pragma unroll
            for (int nt = 0; nt < 4; nt++) {
                int nc = warp_n + nt * 8;
                uint32_t b0 = Bs[kb + sub    ][nc + grp];
                uint32_t b1 = Bs[kb + sub + 4][nc + grp];
                #pragma unroll
                for (int mt = 0; mt < 2; mt++) {
                    asm volatile(
                        "mma.sync.aligned.m16n8k8.row.col.f32.tf32.tf32.f32 "
                        "{%0,%1,%2,%3}, {%4,%5,%6,%7}, {%8,%9}, {%0,%1,%2,%3};"
                        : "+f"(acc[mt][nt][0]), "+f"(acc[mt][nt][1]),
                          "+f"(acc[mt][nt][2]), "+f"(acc[mt][nt][3])
                        : "r"(a[mt][0]), "r"(a[mt][1]), "r"(a[mt][2]), "r"(a[mt][3]),
                          "r"(b0), "r"(b1));
                }
            }
        }
        __syncthreads();
    }

    // epilogue: C fragment c0,c1 at (row=grp, col=2*sub,+1); c2,c3 at row+8
    #pragma unroll
    for (int mt = 0; mt < 2; mt++) {
        int r0 = rb + warp_m + mt * 16 + grp;
        #pragma unroll
        for (int nt = 0; nt < 4; nt++) {
            int c0 = cb + warp_n + nt * 8 + 2 * sub;
            if (r0 < M) {
                C[(size_t)r0 * N + c0]     = acc[mt][nt][0];
                C[(size_t)r0 * N + c0 + 1] = acc[mt][nt][1];
            }
            if (r0 + 8 < M) {
                C[(size_t)(r0 + 8) * N + c0]     = acc[mt][nt][2];
                C[(size_t)(r0 + 8) * N + c0 + 1] = acc[mt][nt][3];
            }
        }
    }
}

// ---------------- attention logits a_s, a_d --------------------------------
template<int MODE>
__global__ void k_att(const float* __restrict__ asrc, const float* __restrict__ adst) {
    const int H = (MODE == 0) ? H1 : H2;
    const float* h = (MODE == 0) ? (const float*)g_h1 : (const float*)g_h2;
    float* oas = (MODE == 0) ? g_as1 : g_as2;
    float* oad = (MODE == 0) ? g_ad1 : g_ad2;
    int w = (blockIdx.x * blockDim.x + threadIdx.x) >> 5;
    int lane = threadIdx.x & 31;
    if (w >= N_NODES * H) return;
    int n = w / H, hh = w % H;
    const float* hp = h + (size_t)n * (H * 128) + hh * 128;
    const float* ap = asrc + hh * 128;
    const float* bp = adst + hh * 128;
    float s = 0.f, d = 0.f;
    #pragma unroll
    for (int j = 0; j < 4; j++) {
        float v = hp[lane + 32 * j];
        s += v * ap[lane + 32 * j];
        d += v * bp[lane + 32 * j];
    }
    #pragma unroll
    for (int o = 16; o; o >>= 1) {
        s += __shfl_xor_sync(~0u, s, o);
        d += __shfl_xor_sync(~0u, d, o);
    }
    if (lane == 0) { oas[w] = s; oad[w] = d; }
}

// ---------------- segment softmax (warp per node, 3 passes) ----------------
template<int MODE>
__global__ void k_softmax() {
    const int H = (MODE == 0) ? H1 : H2;
    const float* as_ = (MODE == 0) ? (const float*)g_as1 : (const float*)g_as2;
    const float* ad_ = (MODE == 0) ? (const float*)g_ad1 : (const float*)g_ad2;
    float* alpha = (MODE == 0) ? g_alpha1 : g_alpha2;
    int n = (blockIdx.x * blockDim.x + threadIdx.x) >> 5;
    int lane = threadIdx.x & 31;
    if (n >= N_NODES) return;
    int beg = g_off[n], end = g_off[n + 1];
    float ad[H1], m[H1], dsum[H1];
    #pragma unroll
    for (int h = 0; h < H; h++) { ad[h] = ad_[n * H + h]; m[h] = -1e30f; dsum[h] = 0.f; }
    for (int i = beg + lane; i < end; i += 32) {
        int s = g_src[i];
        #pragma unroll
        for (int h = 0; h < H; h++) {
            float e = as_[s * H + h] + ad[h];
            e = leaky(e, 0.2f);
            alpha[(size_t)i * H + h] = e;
            m[h] = fmaxf(m[h], e);
        }
    }
    #pragma unroll
    for (int h = 0; h < H; h++)
        #pragma unroll
        for (int o = 16; o; o >>= 1) m[h] = fmaxf(m[h], __shfl_xor_sync(~0u, m[h], o));
    for (int i = beg + lane; i < end; i += 32) {
        #pragma unroll
        for (int h = 0; h < H; h++) {
            float ex = expf(alpha[(size_t)i * H + h] - m[h]);
            alpha[(size_t)i * H + h] = ex;
            dsum[h] += ex;
        }
    }
    #pragma unroll
    for (int h = 0; h < H; h++)
        #pragma unroll
        for (int o = 16; o; o >>= 1) dsum[h] += __shfl_xor_sync(~0u, dsum[h], o);
    float rinv[H1];
    #pragma unroll
    for (int h = 0; h < H; h++) rinv[h] = 1.f / (dsum[h] + 1e-16f);
    for (int i = beg + lane; i < end; i += 32) {
        #pragma unroll
        for (int h = 0; h < H; h++)
            alpha[(size_t)i * H + h] *= rinv[h];
    }
}

// ---------------- layer-1 aggregation (block per node) ---------------------
__global__ void k_agg1(const float* __restrict__ b1) {
    int n = blockIdx.x;
    int t = threadIdx.x;
    int beg = g_off[n], end = g_off[n + 1];
    float acc[H1] = {0.f, 0.f, 0.f, 0.f, 0.f};
    for (int i = beg; i < end; i++) {
        int s = g_src[i];
        float a[H1];
        #pragma unroll
        for (int h = 0; h < H1; h++) a[h] = g_alpha1[(size_t)i * H1 + h];
        const float* hp = g_h1 + (size_t)s * F1;
        #pragma unroll
        for (int h = 0; h < H1; h++) acc[h] += a[h] * hp[h * 128 + t];
    }
    #pragma unroll
    for (int h = 0; h < H1; h++) {
        float v = acc[h] + b1[h * 128 + t];
        g_o1[(size_t)n * F1 + h * 128 + t] = leaky(v, 0.01f);
    }
}

// ---------------- layer-2 aggregation: only bbox entries --------------------
__global__ void k_agg2(const void* __restrict__ bbox, const float* __restrict__ b2,
                       float* __restrict__ out) {
    int i = blockIdx.x;
    int t = threadIdx.x;
    int n = load_idx(bbox, i);
    int beg = g_off[n], end = g_off[n + 1];
    float a0 = 0.f, a1 = 0.f, a2 = 0.f;
    for (int e = beg; e < end; e++) {
        int s = g_src[e];
        float al0 = g_alpha2[(size_t)e * H2 + 0];
        float al1 = g_alpha2[(size_t)e * H2 + 1];
        float al2 = g_alpha2[(size_t)e * H2 + 2];
        const float* hp = g_h2 + (size_t)s * F2;
        a0 += al0 * hp[t];
        a1 += al1 * hp[128 + t];
        a2 += al2 * hp[256 + t];
    }
    float v = (a0 + a1 + a2) * (1.f / 3.f) + b2[t];
    out[(size_t)i * 128 + t] = leaky(v, 0.01f);
}

// ---------------- launch ----------------------------------------------------
extern "C" void kernel_launch(void* const* d_in, const int* in_sizes, int n_in,
                              void* d_out, int out_size) {
    const float *x = nullptr, *W1 = nullptr, *W2 = nullptr, *b1 = nullptr, *b2 = nullptr;
    const float *att_src1 = nullptr, *att_dst1 = nullptr;
    const float *att_src2 = nullptr, *att_dst2 = nullptr;
    const void *ei = nullptr, *bbox = nullptr;
    int n640 = 0, n384 = 0;
    for (int i = 0; i < n_in; i++) {
        switch (in_sizes[i]) {
            case N_NODES * GCN_IN: x    = (const float*)d_in[i]; break;
            case 2 * N_EDGES:      ei   = d_in[i]; break;
            case N_BBOX:           bbox = d_in[i]; break;
            case GCN_IN * F1:      W1   = (const float*)d_in[i]; break;
            case F1 * F2:          W2   = (const float*)d_in[i]; break;
            case C2:               b2   = (const float*)d_in[i]; break;
            case F1:
                if      (n640 == 0) att_src1 = (const float*)d_in[i];
                else if (n640 == 1) att_dst1 = (const float*)d_in[i];
                else                b1       = (const float*)d_in[i];
                n640++; break;
            case F2:
                if (n384 == 0) att_src2 = (const float*)d_in[i];
                else           att_dst2 = (const float*)d_in[i];
                n384++; break;
            default: break;
        }
    }
    float* out = (float*)d_out;

    // dtype sniff + CSR build
    k_detect<<<1, 1>>>(ei);
    k_zero<<<(N_NODES + 255) / 256, 256>>>();
    k_hist<<<(ET + 255) / 256, 256>>>(ei);
    k_scan1<<<NB_SCAN, 1024>>>();
    k_scan2<<<1, 32>>>();
    k_scan3<<<NB_SCAN, 1024>>>();
    k_scatter<<<(ET + 255) / 256, 256>>>(ei);

    // layer 1
    {
        dim3 g(F1 / 64, (N_NODES + 127) / 128);
        gemm_tf32<0><<<g, 256>>>(x, W1);
    }
    k_att<0><<<(N_NODES * H1 * 32 + 255) / 256, 256>>>(att_src1, att_dst1);
    k_softmax<0><<<(N_NODES * 32 + 255) / 256, 256>>>();
    k_agg1<<<N_NODES, 128>>>(b1);

    // layer 2
    {
        dim3 g(F2 / 64, (N_NODES + 127) / 128);
        gemm_tf32<1><<<g, 256>>>(nullptr, W2);
    }
    k_att<1><<<(N_NODES * H2 * 32 + 255) / 256, 256>>>(att_src2, att_dst2);
    k_softmax<1><<<(N_NODES * 32 + 255) / 256, 256>>>();
    k_agg2<<<N_BBOX, 128>>>(bbox, b2, out);
}